// round 11
// baseline (speedup 1.0000x reference)
#include <cuda_runtime.h>
#include <cuda_fp16.h>
#include <cstdint>

// Problem constants (fixed: B=8192, D=128)
#define NB 8192
#define ND 128
#define NFJ 128                     // fine col blocks (64 cols each)
#define GRID 444                    // 3 CTAs per SM
#define NTILES 4160                 // sum_{ti<64} (128 - 2*ti)
#define MARGIN 0.5f
#define STRB 272                    // padded row stride in bytes -> conflict-free ldmatrix
#define TILE_A (128 * STRB)         // 34816
#define TILE_B (64 * STRB)          // 17408

// Device scratch (no allocation allowed)
__device__ __align__(16) __half g_af16[NB * ND];
__device__ float g_posd[NB];
__device__ int   g_lab[NB];
__device__ int   g_maxbits[NB];
__device__ int   g_done;

// ---------------------------------------------------------------------------
// helpers
// ---------------------------------------------------------------------------
__device__ __forceinline__ uint32_t smem_u32(const void* p) {
    uint32_t a;
    asm("{ .reg .u64 t; cvta.to.shared.u64 t, %1; cvt.u32.u64 %0, t; }" : "=r"(a) : "l"(p));
    return a;
}
__device__ __forceinline__ void cpasync16(uint32_t dst, const void* src) {
    asm volatile("cp.async.cg.shared.global [%0], [%1], 16;" :: "r"(dst), "l"(src));
}
__device__ __forceinline__ void mma16816(float* c, const uint32_t* a, const uint32_t* b) {
    asm volatile(
        "mma.sync.aligned.m16n8k16.row.col.f32.f16.f16.f32 "
        "{%0,%1,%2,%3}, {%4,%5,%6,%7}, {%8,%9}, {%0,%1,%2,%3};"
        : "+f"(c[0]), "+f"(c[1]), "+f"(c[2]), "+f"(c[3])
        : "r"(a[0]), "r"(a[1]), "r"(a[2]), "r"(a[3]), "r"(b[0]), "r"(b[1]));
}
__device__ __forceinline__ void ldsm4(uint32_t* r, uint32_t addr) {
    asm volatile("ldmatrix.sync.aligned.m8n8.x4.shared.b16 {%0,%1,%2,%3}, [%4];"
        : "=r"(r[0]), "=r"(r[1]), "=r"(r[2]), "=r"(r[3]) : "r"(addr));
}

// ---------------------------------------------------------------------------
// Kernel 1: normalize anchors -> fp16; pos_dist; labels; init max.
// Four rows per warp (MLP 8).
// ---------------------------------------------------------------------------
__global__ void prep_kernel(const float* __restrict__ anchor,
                            const float* __restrict__ positive,
                            const int* __restrict__ labels) {
    int gw   = (blockIdx.x * blockDim.x + threadIdx.x) >> 5;
    int lane = threadIdx.x & 31;
    int r0 = gw * 4;
    if (r0 >= NB) return;
    if (gw == 0 && lane == 0) g_done = 0;

    float4 av[4], pv[4];
    #pragma unroll
    for (int k = 0; k < 4; k++) {
        av[k] = reinterpret_cast<const float4*>(anchor   + (size_t)(r0 + k) * ND)[lane];
        pv[k] = reinterpret_cast<const float4*>(positive + (size_t)(r0 + k) * ND)[lane];
    }

    float sa[4], sp[4];
    #pragma unroll
    for (int k = 0; k < 4; k++) {
        sa[k] = av[k].x*av[k].x + av[k].y*av[k].y + av[k].z*av[k].z + av[k].w*av[k].w;
        sp[k] = pv[k].x*pv[k].x + pv[k].y*pv[k].y + pv[k].z*pv[k].z + pv[k].w*pv[k].w;
    }
    #pragma unroll
    for (int o = 16; o > 0; o >>= 1)
        #pragma unroll
        for (int k = 0; k < 4; k++) {
            sa[k] += __shfl_xor_sync(0xffffffffu, sa[k], o);
            sp[k] += __shfl_xor_sync(0xffffffffu, sp[k], o);
        }

    float d2[4];
    #pragma unroll
    for (int k = 0; k < 4; k++) {
        float ia = 1.0f / fmaxf(sqrtf(sa[k]), 1e-12f);
        float ip = 1.0f / fmaxf(sqrtf(sp[k]), 1e-12f);
        float an[4] = {av[k].x*ia, av[k].y*ia, av[k].z*ia, av[k].w*ia};
        float pn[4] = {pv[k].x*ip, pv[k].y*ip, pv[k].z*ip, pv[k].w*ip};

        __half2 ha; ha.x = __float2half_rn(an[0]); ha.y = __float2half_rn(an[1]);
        __half2 hb; hb.x = __float2half_rn(an[2]); hb.y = __float2half_rn(an[3]);
        size_t base = (size_t)(r0 + k) * ND + lane * 4;
        reinterpret_cast<__half2*>(g_af16 + base)[0] = ha;
        reinterpret_cast<__half2*>(g_af16 + base)[1] = hb;

        float s = 0.0f;
        #pragma unroll
        for (int q = 0; q < 4; q++) {
            float d = an[q] - pn[q];
            s = fmaf(d, d, s);
        }
        d2[k] = s;
    }
    #pragma unroll
    for (int o = 16; o > 0; o >>= 1)
        #pragma unroll
        for (int k = 0; k < 4; k++)
            d2[k] += __shfl_xor_sync(0xffffffffu, d2[k], o);

    if (lane < 4) {
        g_posd[r0 + lane]    = d2[lane];
        g_lab[r0 + lane]     = labels[r0 + lane];
        g_maxbits[r0 + lane] = 0;
    }
}

// ---------------------------------------------------------------------------
// Kernel 2: symmetric max-gram, fp16 mma.sync, 3 CTAs/SM (24 warps).
// Tile = 128 rows x 64 cols; 8 warps as 4(M) x 2(N): warp tile 32x32.
// SMEM: [A 128rows][B0 64rows][B1 64rows] = 69632 B. Fine triangular walk
// over (ti, tjf) with tjf >= 2*ti (4160 tiles); col-max applied to every
// tile (idempotent on diagonal blocks). Fused last-CTA loss reduction.
// ---------------------------------------------------------------------------
__global__ void __launch_bounds__(256, 3) maxgram_sym(float* __restrict__ out) {
    extern __shared__ char dsm[];
    __shared__ int labJ[2][64];
    __shared__ int s_last;
    __shared__ float red[256];

    const int tid  = threadIdx.x;
    const int lane = tid & 31;
    const int wid  = tid >> 5;
    const int wm   = wid & 3;         // M quarter (32 rows)
    const int wn   = wid >> 2;        // N half (32 cols)
    const int g    = lane >> 2;
    const int q    = lane & 3;

    const uint32_t smb = smem_u32(dsm);

    const uint32_t aoff = (uint32_t)(wm * 32 + (lane & 15)) * STRB + (uint32_t)(lane >> 4) * 16;
    const uint32_t boff = (uint32_t)(wn * 32 + ((lane >> 4) << 3) + (lane & 7)) * STRB
                        + (uint32_t)((lane >> 3) & 1) * 16;

    // tile range: 4160 tiles over 444 CTAs (first 164 get 10, rest 9)
    const int bid = blockIdx.x;
    const int L   = bid * 9 + min(bid, 164);
    const int MYT = 9 + (bid < 164 ? 1 : 0);

    // decode starting tile (row-major over tjf >= 2*ti)
    int ti = 0, base = 0;
    while (base + (NFJ - 2 * ti) <= L) { base += NFJ - 2 * ti; ti++; }
    int tjf = 2 * ti + (L - base);

    auto loadA = [&](int t) {
        const int i0 = t * 128;
        for (int idx = tid; idx < 2048; idx += 256) {
            int r = idx >> 4, c = idx & 15;
            cpasync16(smb + r * STRB + c * 16,
                      g_af16 + (size_t)(i0 + r) * ND + c * 8);
        }
    };
    auto loadB = [&](int t, int buf) {
        const int j0 = t * 64;
        uint32_t bb = smb + TILE_A + buf * TILE_B;
        for (int idx = tid; idx < 1024; idx += 256) {
            int r = idx >> 4, c = idx & 15;
            cpasync16(bb + r * STRB + c * 16,
                      g_af16 + (size_t)(j0 + r) * ND + c * 8);
        }
        if (tid < 64) labJ[buf][tid] = g_lab[j0 + tid];
    };

    int lr[2][2];
    auto loadLr = [&](int t) {
        #pragma unroll
        for (int mt = 0; mt < 2; mt++) {
            int r = t * 128 + wm * 32 + mt * 16 + g;
            lr[mt][0] = g_lab[r];
            lr[mt][1] = g_lab[r + 8];
        }
    };

    float mx[2][2];
    #pragma unroll
    for (int mt = 0; mt < 2; mt++) { mx[mt][0] = -3.0f; mx[mt][1] = -3.0f; }

    auto flushRows = [&](int t) {
        #pragma unroll
        for (int mt = 0; mt < 2; mt++)
            #pragma unroll
            for (int r = 0; r < 2; r++) {
                float v = mx[mt][r];
                v = fmaxf(v, __shfl_xor_sync(0xffffffffu, v, 1));
                v = fmaxf(v, __shfl_xor_sync(0xffffffffu, v, 2));
                if (q == 0)
                    atomicMax(&g_maxbits[t * 128 + wm * 32 + mt * 16 + g + r * 8],
                              __float_as_int(fmaxf(v + 2.0f, 0.0f)));
                mx[mt][r] = -3.0f;
            }
    };

    // prologue
    loadA(ti);
    loadB(tjf, 0);
    asm volatile("cp.async.commit_group;");
    loadLr(ti);

    for (int n = 0; n < MYT; n++) {
        const int buf = n & 1;

        int ti_n = ti, tjf_n = tjf + 1;
        if (tjf_n == NFJ) { ti_n = ti + 1; tjf_n = 2 * ti_n; }

        asm volatile("cp.async.wait_group 0;" ::: "memory");
        __syncthreads();

        if (n + 1 < MYT) {
            loadB(tjf_n, buf ^ 1);
            asm volatile("cp.async.commit_group;");
        }

        // ---- compute tile (ti, tjf) ----
        const uint32_t Abase = smb + aoff;
        const uint32_t Bbase = smb + TILE_A + buf * TILE_B + boff;

        float acc[2][4][4];
        #pragma unroll
        for (int mt = 0; mt < 2; mt++)
            #pragma unroll
            for (int nt = 0; nt < 4; nt++)
                #pragma unroll
                for (int e = 0; e < 4; e++) acc[mt][nt][e] = 0.0f;

        #pragma unroll
        for (int ks = 0; ks < 8; ks++) {
            const uint32_t ko = ks * 32;

            uint32_t a[2][4], b[4][2];
            #pragma unroll
            for (int mt = 0; mt < 2; mt++)
                ldsm4(a[mt], Abase + mt * (16 * STRB) + ko);
            #pragma unroll
            for (int p = 0; p < 2; p++) {
                uint32_t rb[4];
                ldsm4(rb, Bbase + p * (16 * STRB) + ko);
                b[2*p][0] = rb[0]; b[2*p][1] = rb[1];
                b[2*p+1][0] = rb[2]; b[2*p+1][1] = rb[3];
            }
            #pragma unroll
            for (int mt = 0; mt < 2; mt++)
                #pragma unroll
                for (int nt = 0; nt < 4; nt++)
                    mma16816(acc[mt][nt], a[mt], b[nt]);
        }

        // ---- epilogue: mask, row-max, column-max ----
        float cmax[4][2];
        #pragma unroll
        for (int nt = 0; nt < 4; nt++) { cmax[nt][0] = -3.0f; cmax[nt][1] = -3.0f; }

        #pragma unroll
        for (int nt = 0; nt < 4; nt++) {
            int c0 = wn * 32 + nt * 8 + q * 2;
            int l0 = labJ[buf][c0], l1 = labJ[buf][c0 + 1];
            #pragma unroll
            for (int mt = 0; mt < 2; mt++) {
                float v0 = (l0 == lr[mt][0]) ? -3.0f : acc[mt][nt][0];
                float v1 = (l1 == lr[mt][0]) ? -3.0f : acc[mt][nt][1];
                float v2 = (l0 == lr[mt][1]) ? -3.0f : acc[mt][nt][2];
                float v3 = (l1 == lr[mt][1]) ? -3.0f : acc[mt][nt][3];
                mx[mt][0] = fmaxf(mx[mt][0], fmaxf(v0, v1));
                mx[mt][1] = fmaxf(mx[mt][1], fmaxf(v2, v3));
                cmax[nt][0] = fmaxf(cmax[nt][0], fmaxf(v0, v2));
                cmax[nt][1] = fmaxf(cmax[nt][1], fmaxf(v1, v3));
            }
        }

        // column-side merge (idempotent on diagonal blocks)
        #pragma unroll
        for (int nt = 0; nt < 4; nt++)
            #pragma unroll
            for (int e = 0; e < 2; e++) {
                float v = cmax[nt][e];
                v = fmaxf(v, __shfl_xor_sync(0xffffffffu, v, 4));
                v = fmaxf(v, __shfl_xor_sync(0xffffffffu, v, 8));
                v = fmaxf(v, __shfl_xor_sync(0xffffffffu, v, 16));
                if (g == 0)
                    atomicMax(&g_maxbits[tjf * 64 + wn * 32 + nt * 8 + q * 2 + e],
                              __float_as_int(fmaxf(v + 2.0f, 0.0f)));
            }

        if (n + 1 < MYT) {
            if (ti_n != ti) {
                flushRows(ti);
                __syncthreads();          // all warps done reading A
                loadA(ti_n);
                asm volatile("cp.async.commit_group;");
                loadLr(ti_n);
            }
            ti = ti_n; tjf = tjf_n;
        }
    }
    flushRows(ti);

    // ---- fused finalize: last CTA reduces the loss ----
    __threadfence();
    if (tid == 0) s_last = (atomicAdd(&g_done, 1) == GRID - 1) ? 1 : 0;
    __syncthreads();
    if (s_last) {
        float s = 0.0f;
        for (int i = tid; i < NB; i += 256) {
            float gmax = __int_as_float(__ldcg(&g_maxbits[i])) - 2.0f;
            float neg  = fmaxf(2.0f - 2.0f * gmax, 0.0f);
            float l    = __ldcg(&g_posd[i]) - neg + MARGIN;
            s += fmaxf(l, 0.0f);
        }
        red[tid] = s;
        __syncthreads();
        #pragma unroll
        for (int stride = 128; stride > 0; stride >>= 1) {
            if (tid < stride) red[tid] += red[tid + stride];
            __syncthreads();
        }
        if (tid == 0) out[0] = red[0] / (float)NB;
    }
}

extern "C" void kernel_launch(void* const* d_in, const int* in_sizes, int n_in,
                              void* d_out, int out_size) {
    const float* anchor   = (const float*)d_in[0];
    const float* positive = (const float*)d_in[1];
    const int*   labels   = (const int*)d_in[2];   // JAX x64 disabled: int64 -> int32
    float*       out      = (float*)d_out;

    prep_kernel<<<NB / 32, 256>>>(anchor, positive, labels);

    const int smem = TILE_A + 2 * TILE_B;   // 69632 B -> 3 CTAs/SM
    cudaFuncSetAttribute(maxgram_sym, cudaFuncAttributeMaxDynamicSharedMemorySize, smem);
    maxgram_sym<<<GRID, 256, smem>>>(out);
}